// round 3
// baseline (speedup 1.0000x reference)
#include <cuda_runtime.h>
#include <cstdint>

#define B_   50
#define T_   2048
#define D_   65
#define G4   260
#define BT   (B_ * T_)
#define HP   80        // padded h storage per buffer (quarters of 20, halves of 36 both 16B-aligned)
#define NL   3

// Precomputed x@W + b : [B*T, 260]
__device__ float g_xw[(size_t)BT * G4];
// Top-layer hidden states for the dense epilogue: [B*T, 65]
__device__ float g_hs[(size_t)BT * D_];

// ---------------------------------------------------------------------------
// helpers
// ---------------------------------------------------------------------------
__device__ __forceinline__ void ffma2(uint64_t& acc, uint64_t a, uint64_t b) {
    asm("fma.rn.f32x2 %0, %1, %2, %0;" : "+l"(acc) : "l"(a), "l"(b));
}
__device__ __forceinline__ float hsum2(uint64_t v) {
    float lo, hi;
    asm("mov.b64 {%0, %1}, %2;" : "=f"(lo), "=f"(hi) : "l"(v));
    return lo + hi;
}
__device__ __forceinline__ uint64_t pack2(float lo, float hi) {
    uint64_t r;
    asm("mov.b64 %0, {%1, %2};" : "=l"(r) : "f"(lo), "f"(hi));
    return r;
}
__device__ __forceinline__ float tanh_fast(float x) {
    float e = __expf(2.0f * x);
    return fmaf(-2.0f, __fdividef(1.0f, 1.0f + e), 1.0f);
}

// ---------------------------------------------------------------------------
// GEMM: g_xw[r, c] = x[r, :] @ W[:, c] + b[c]     (r over B*T)
// grid (BT/32, 2), block (130, 4)
// ---------------------------------------------------------------------------
__global__ void __launch_bounds__(520) gemm_xw_kernel(
    const float* __restrict__ x, const float* __restrict__ W,
    const float* __restrict__ b)
{
    __shared__ float Ws[D_][130];
    __shared__ float xs[32][D_];

    const int col = threadIdx.x;            // 0..129
    const int ry  = threadIdx.y;            // 0..3
    const int tid = ry * 130 + col;
    const int half = blockIdx.y;

    for (int i = tid; i < D_ * 130; i += 520) {
        int k = i / 130, c = i % 130;
        Ws[k][c] = W[(size_t)k * G4 + half * 130 + c];
    }
    const size_t row0 = (size_t)blockIdx.x * 32;
    for (int i = tid; i < 32 * D_; i += 520)
        xs[i / D_][i % D_] = x[row0 * D_ + i];
    __syncthreads();

    const float bc = b[half * 130 + col];
    for (int r = ry; r < 32; r += 4) {
        float acc = bc;
#pragma unroll
        for (int k = 0; k < D_; k++)
            acc = fmaf(xs[r][k], Ws[k][col], acc);
        g_xw[(row0 + r) * G4 + half * 130 + col] = acc;
    }
}

// ---------------------------------------------------------------------------
// LSTM: one CTA per batch element. 260 threads; thread = (unit j, quarter q).
// Lanes 4j..4j+3 own the 4 gate columns of unit j; gates never leave the warp.
// ---------------------------------------------------------------------------
struct GateConst { float ak, am, aa; };

// reduce 4 packed accumulators -> z's -> activation -> cell update
__device__ __forceinline__ float gate_phase(
    uint64_t a0, uint64_t a1, uint64_t a2, uint64_t a3,
    float zadd, float& c, unsigned mask, int base, int q, GateConst gc)
{
    float s0 = hsum2(a0), s1 = hsum2(a1), s2 = hsum2(a2), s3 = hsum2(a3);
    s0 += __shfl_xor_sync(mask, s0, 1);
    s1 += __shfl_xor_sync(mask, s1, 1);
    s2 += __shfl_xor_sync(mask, s2, 1);
    s3 += __shfl_xor_sync(mask, s3, 1);
    s0 += __shfl_xor_sync(mask, s0, 2);
    s1 += __shfl_xor_sync(mask, s1, 2);
    s2 += __shfl_xor_sync(mask, s2, 2);
    s3 += __shfl_xor_sync(mask, s3, 2);
    // every lane now has all four full sums; lane q activates gate q only
    float zq = (q == 0) ? s0 : (q == 1) ? s1 : (q == 2) ? s2 : s3;
    zq += zadd;
    float e   = __expf(gc.ak * zq);
    float act = fmaf(gc.am, __fdividef(1.0f, 1.0f + e), gc.aa);
    float ig = __shfl_sync(mask, act, base + 0);
    float fg = __shfl_sync(mask, act, base + 1);
    float gg = __shfl_sync(mask, act, base + 2);
    float og = __shfl_sync(mask, act, base + 3);
    float cn = fmaf(fg, c, ig * gg);
    c = cn;
    return og * tanh_fast(cn);
}

__global__ void __launch_bounds__(260, 1) lstm_kernel(
    const float* __restrict__ W,   // [65, 260]
    const float* __restrict__ U,   // [65, 260]
    const float* __restrict__ b)   // [260]
{
    // double-buffered hidden state per layer
    __shared__ __align__(16) float hs[NL][2][HP];

    const int tid  = threadIdx.x;
    const int bb   = blockIdx.x;
    const int j    = tid >> 2;             // unit 0..64
    const int q    = tid & 3;              // quarter / gate lane
    const int lane = tid & 31;
    const unsigned mask = (tid >= 256) ? 0xFu : 0xFFFFFFFFu;
    const int base = lane & ~3;

    // ---- Set A (layers 1,2): concat [inp(36*2) ; h(36*2)] quarter weights ----
    // q<2 -> W rows [36q, 36q+36);  q>=2 -> U rows [36(q-2), ...)
    uint64_t Wa[4][18];
    {
        const float* M = (q < 2) ? W : U;
        const int rb = 36 * (q & 1);
#pragma unroll
        for (int g = 0; g < 4; g++)
#pragma unroll
            for (int i = 0; i < 18; i++) {
                int k0 = rb + 2 * i, k1 = k0 + 1;
                float w0 = (k0 < D_) ? M[(size_t)k0 * G4 + g * D_ + j] : 0.0f;
                float w1 = (k1 < D_) ? M[(size_t)k1 * G4 + g * D_ + j] : 0.0f;
                Wa[g][i] = pack2(w0, w1);
            }
    }
    // ---- Set B (layer 0, U only): quarters of 20 rows ----
    uint64_t Ub[4][10];
    {
        const int rb = 20 * q;
#pragma unroll
        for (int g = 0; g < 4; g++)
#pragma unroll
            for (int i = 0; i < 10; i++) {
                int k0 = rb + 2 * i, k1 = k0 + 1;
                float u0 = (k0 < D_) ? U[(size_t)k0 * G4 + g * D_ + j] : 0.0f;
                float u1 = (k1 < D_) ? U[(size_t)k1 * G4 + g * D_ + j] : 0.0f;
                Ub[g][i] = pack2(u0, u1);
            }
    }
    const float bq = b[q * D_ + j];                       // layers 1,2 (layer 0 bias folded in xw)
    const GateConst gc = (q == 2) ? GateConst{2.0f, -2.0f, 1.0f}
                                  : GateConst{-1.0f, 1.0f, 0.0f};

    for (int i = tid; i < NL * 2 * HP; i += 260) ((float*)hs)[i] = 0.0f;

    const float* xwp  = g_xw + (size_t)bb * T_ * G4 + q * D_ + j;
    float*       hout = g_hs + (size_t)bb * T_ * D_;
    float c0 = 0.f, c1 = 0.f, c2 = 0.f;
    float xwv = xwp[0];
    __syncthreads();

    int p = 0;   // read-buffer parity
    for (int t = 0; t < T_; t++) {
        const int pn = p ^ 1;
        // prefetch next timestep's xw (consumed next iteration)
        float xwn = xwp[(size_t)(t + 1 < T_ ? t + 1 : t) * G4];

        // ================= layer 0: U-dot only (quarters of 20) =============
        {
            uint64_t a0 = 0, a1 = 0, a2 = 0, a3 = 0;
            const ulonglong2* src =
                reinterpret_cast<const ulonglong2*>(&hs[0][p][20 * q]);
#pragma unroll
            for (int i = 0; i < 5; i++) {
                ulonglong2 v = src[i];
                ffma2(a0, v.x, Ub[0][2 * i]); ffma2(a0, v.y, Ub[0][2 * i + 1]);
                ffma2(a1, v.x, Ub[1][2 * i]); ffma2(a1, v.y, Ub[1][2 * i + 1]);
                ffma2(a2, v.x, Ub[2][2 * i]); ffma2(a2, v.y, Ub[2][2 * i + 1]);
                ffma2(a3, v.x, Ub[3][2 * i]); ffma2(a3, v.y, Ub[3][2 * i + 1]);
            }
            float hn = gate_phase(a0, a1, a2, a3, xwv, c0, mask, base, q, gc);
            if (q == 0) hs[0][pn][j] = hn;
        }
        __syncthreads();

        // ================= layers 1, 2: concat dot (halves of 36) ===========
#pragma unroll
        for (int l = 1; l < NL; l++) {
            uint64_t a0 = 0, a1 = 0, a2 = 0, a3 = 0;
            // q<2 reads lower layer's NEW h; q>=2 reads own layer's OLD h
            const float* arr = (q < 2) ? &hs[l - 1][pn][0] : &hs[l][p][0];
            const ulonglong2* src =
                reinterpret_cast<const ulonglong2*>(arr + 36 * (q & 1));
#pragma unroll
            for (int i = 0; i < 9; i++) {
                ulonglong2 v = src[i];
                ffma2(a0, v.x, Wa[0][2 * i]); ffma2(a0, v.y, Wa[0][2 * i + 1]);
                ffma2(a1, v.x, Wa[1][2 * i]); ffma2(a1, v.y, Wa[1][2 * i + 1]);
                ffma2(a2, v.x, Wa[2][2 * i]); ffma2(a2, v.y, Wa[2][2 * i + 1]);
                ffma2(a3, v.x, Wa[3][2 * i]); ffma2(a3, v.y, Wa[3][2 * i + 1]);
            }
            float& c = (l == 1) ? c1 : c2;
            float hn = gate_phase(a0, a1, a2, a3, bq, c, mask, base, q, gc);
            if (q == 0) {
                hs[l][pn][j] = hn;
                if (l == NL - 1) hout[(size_t)t * D_ + j] = hn;
            }
            __syncthreads();
        }

        xwv = xwn;
        p = pn;
    }
}

// ---------------------------------------------------------------------------
// Dense(65) epilogue: out[r,:] = g_hs[r,:] @ Wd + bd
// ---------------------------------------------------------------------------
#define ROWS_PB 32
__global__ void __launch_bounds__(260) dense_kernel(
    const float* __restrict__ Wd,
    const float* __restrict__ bd,
    float* __restrict__ out)
{
    __shared__ float Wds[D_ * D_];
    __shared__ float bds[D_];
    __shared__ float hrow[ROWS_PB][D_];

    const int tx  = threadIdx.x;           // 0..64
    const int ty  = threadIdx.y;           // 0..3
    const int tid = ty * D_ + tx;

    for (int i = tid; i < D_ * D_; i += 260) Wds[i] = Wd[i];
    if (tid < D_) bds[tid] = bd[tid];
    const size_t row0 = (size_t)blockIdx.x * ROWS_PB;
    for (int i = tid; i < ROWS_PB * D_; i += 260)
        hrow[i / D_][i % D_] = g_hs[row0 * D_ + i];
    __syncthreads();

    for (int r = ty; r < ROWS_PB; r += 4) {
        float acc = bds[tx];
#pragma unroll
        for (int k = 0; k < D_; k++)
            acc = fmaf(hrow[r][k], Wds[k * D_ + tx], acc);
        out[(row0 + r) * D_ + tx] = acc;
    }
}

// ---------------------------------------------------------------------------
extern "C" void kernel_launch(void* const* d_in, const int* in_sizes, int n_in,
                              void* d_out, int out_size)
{
    const float* x  = (const float*)d_in[0];
    const float* W  = (const float*)d_in[1];
    const float* U  = (const float*)d_in[2];
    const float* b  = (const float*)d_in[3];
    const float* Wd = (const float*)d_in[4];
    const float* bd = (const float*)d_in[5];
    float* out = (float*)d_out;

    gemm_xw_kernel<<<dim3(BT / 32, 2), dim3(130, 4)>>>(x, W, b);
    lstm_kernel<<<B_, G4>>>(W, U, b);
    dense_kernel<<<BT / ROWS_PB, dim3(D_, 4)>>>(Wd, bd, out);
}

// round 4
// speedup vs baseline: 2.3146x; 2.3146x over previous
#include <cuda_runtime.h>
#include <cstdint>

#define B_  50
#define T_  2048
#define D_  65
#define G4  260
#define BT  (B_ * T_)
#define KP  68          // K padded to 17*4 (16B multiples)
#define NL  3

// Precomputed x@W + b : [B*T, 260]
__device__ float g_xw[(size_t)BT * G4];
// Top-layer hidden states for dense epilogue: [B*T, 65]
__device__ float g_hs[(size_t)BT * D_];

// ---------------------------------------------------------------------------
// helpers
// ---------------------------------------------------------------------------
__device__ __forceinline__ void ffma2(uint64_t& acc, uint64_t a, uint64_t b) {
    asm("fma.rn.f32x2 %0, %1, %2, %0;" : "+l"(acc) : "l"(a), "l"(b));
}
__device__ __forceinline__ uint64_t fadd2(uint64_t a, uint64_t b) {
    uint64_t r;
    asm("add.rn.f32x2 %0, %1, %2;" : "=l"(r) : "l"(a), "l"(b));
    return r;
}
__device__ __forceinline__ float hsum2(uint64_t v) {
    float lo, hi;
    asm("mov.b64 {%0, %1}, %2;" : "=f"(lo), "=f"(hi) : "l"(v));
    return lo + hi;
}
__device__ __forceinline__ uint64_t pack2(float lo, float hi) {
    uint64_t r;
    asm("mov.b64 %0, {%1, %2};" : "=l"(r) : "f"(lo), "f"(hi));
    return r;
}
__device__ __forceinline__ float tanh_fast(float x) {
    float e = __expf(2.0f * x);
    return fmaf(-2.0f, __fdividef(1.0f, 1.0f + e), 1.0f);
}

// dot of 68 floats (16B-aligned SMEM src) with packed weight column (34 u64).
// 4 independent accumulator chains for ILP.
__device__ __forceinline__ float dot68(const float* __restrict__ src,
                                       const uint64_t* __restrict__ Wc) {
    uint64_t a0 = 0, a1 = 0, a2 = 0, a3 = 0;
    const ulonglong2* s2 = reinterpret_cast<const ulonglong2*>(src);
#pragma unroll
    for (int i = 0; i < 17; i++) {
        ulonglong2 v = s2[i];
        if (i & 1) { ffma2(a2, v.x, Wc[2 * i]); ffma2(a3, v.y, Wc[2 * i + 1]); }
        else       { ffma2(a0, v.x, Wc[2 * i]); ffma2(a1, v.y, Wc[2 * i + 1]); }
    }
    return hsum2(fadd2(fadd2(a0, a1), fadd2(a2, a3)));
}

// load a padded weight column (68 rows, zeros past 65) into 34 packed regs
__device__ __forceinline__ void load_col(uint64_t* Wc,
                                         const float* __restrict__ M, int col) {
#pragma unroll
    for (int i = 0; i < 34; i++) {
        int k0 = 2 * i, k1 = 2 * i + 1;
        float w0 = (k0 < D_) ? M[(size_t)k0 * G4 + col] : 0.0f;
        float w1 = (k1 < D_) ? M[(size_t)k1 * G4 + col] : 0.0f;
        Wc[i] = pack2(w0, w1);
    }
}

// ---------------------------------------------------------------------------
// GEMM: g_xw[r, c] = x[r,:] @ W[:,c] + b[c].  Thread owns column c (W col in
// registers); rows streamed through SMEM in chunks of 32. 128 rows per block.
// ---------------------------------------------------------------------------
#define GR 128
__global__ void __launch_bounds__(G4, 2) gemm_xw_kernel(
    const float* __restrict__ x, const float* __restrict__ W,
    const float* __restrict__ b)
{
    __shared__ __align__(16) float xs[2][32][KP];
    const int c = threadIdx.x;
    uint64_t Wc[34];
    load_col(Wc, W, c);
    const float bc = b[c];
    const size_t row0 = (size_t)blockIdx.x * GR;

    // stage chunk 0
    for (int i = c; i < 32 * KP; i += G4) {
        int r = i / KP, cc = i % KP;
        xs[0][r][cc] = (cc < D_) ? x[(row0 + r) * D_ + cc] : 0.0f;
    }
    __syncthreads();

    for (int ch = 0; ch < GR / 32; ch++) {
        int buf = ch & 1;
        // stage next chunk (no barrier needed before: writes go to other buf)
        if (ch + 1 < GR / 32) {
            for (int i = c; i < 32 * KP; i += G4) {
                int r = i / KP, cc = i % KP;
                xs[buf ^ 1][r][cc] =
                    (cc < D_) ? x[(row0 + (ch + 1) * 32 + r) * D_ + cc] : 0.0f;
            }
        }
        for (int r = 0; r < 32; r++)
            g_xw[(row0 + ch * 32 + r) * G4 + c] = bc + dot68(xs[buf][r], Wc);
        __syncthreads();
    }
}

// ---------------------------------------------------------------------------
// LSTM: one CTA / batch element; 260 threads; tid = 4*unit + gate.
// Gates stay in-warp: z -> act per lane, 3 shfls gather i,f,g,o to lane g=0.
// ---------------------------------------------------------------------------
__global__ void __launch_bounds__(G4, 1) lstm_kernel(
    const float* __restrict__ W,
    const float* __restrict__ U,
    const float* __restrict__ b)
{
    __shared__ __align__(16) float hs[NL][2][KP];  // double-buffered h per layer

    const int tid  = threadIdx.x;
    const int bb   = blockIdx.x;
    const int j    = tid >> 2;       // unit 0..64
    const int g    = tid & 3;        // gate: 0=i 1=f 2=g 3=o
    const int lane = tid & 31;
    const int base = lane & ~3;
    const unsigned mask = (tid >= 256) ? 0xFu : 0xFFFFFFFFu;
    const int col = g * D_ + j;      // z-column in [0,260)

    uint64_t Wc[34], Uc[34];
    load_col(Wc, W, col);
    load_col(Uc, U, col);
    const float bcol = b[col];
    // activation constants: gate 2 -> tanh, else sigmoid
    const float ak = (g == 2) ?  2.0f : -1.0f;
    const float am = (g == 2) ? -2.0f :  1.0f;
    const float aa = (g == 2) ?  1.0f :  0.0f;

    for (int i = tid; i < NL * 2 * KP; i += G4) ((float*)hs)[i] = 0.0f;
    float c0 = 0.f, c1 = 0.f, c2 = 0.f;

    const float* xwp  = g_xw + (size_t)bb * T_ * G4 + col;
    float*       hout = g_hs + (size_t)bb * T_ * D_;
    float xwv = xwp[0];
    __syncthreads();

    int p = 0;
    for (int t = 0; t < T_; t++) {
        const int pn = p ^ 1;
        float xwn = xwp[(size_t)(t + 1 < T_ ? t + 1 : t) * G4];  // prefetch

        // ---------------- layer 0: z = xw + U.h0[p] -----------------------
        {
            float z = xwv + dot68(hs[0][p], Uc);
            float e   = __expf(ak * z);
            float act = fmaf(am, __fdividef(1.0f, 1.0f + e), aa);
            float ig = __shfl_sync(mask, act, base + 0);
            float fg = __shfl_sync(mask, act, base + 1);
            float gg = __shfl_sync(mask, act, base + 2);
            float og = __shfl_sync(mask, act, base + 3);
            if (g == 0) {
                c0 = fmaf(fg, c0, ig * gg);
                hs[0][pn][j] = og * tanh_fast(c0);
            }
        }
        __syncthreads();

        // ---------------- layer 1: z = b + W.h0[pn] + U.h1[p] -------------
        {
            float z = bcol + dot68(hs[0][pn], Wc) + dot68(hs[1][p], Uc);
            float e   = __expf(ak * z);
            float act = fmaf(am, __fdividef(1.0f, 1.0f + e), aa);
            float ig = __shfl_sync(mask, act, base + 0);
            float fg = __shfl_sync(mask, act, base + 1);
            float gg = __shfl_sync(mask, act, base + 2);
            float og = __shfl_sync(mask, act, base + 3);
            if (g == 0) {
                c1 = fmaf(fg, c1, ig * gg);
                hs[1][pn][j] = og * tanh_fast(c1);
            }
        }
        __syncthreads();

        // ---------------- layer 2: z = b + W.h1[pn] + U.h2[p] -------------
        {
            float z = bcol + dot68(hs[1][pn], Wc) + dot68(hs[2][p], Uc);
            float e   = __expf(ak * z);
            float act = fmaf(am, __fdividef(1.0f, 1.0f + e), aa);
            float ig = __shfl_sync(mask, act, base + 0);
            float fg = __shfl_sync(mask, act, base + 1);
            float gg = __shfl_sync(mask, act, base + 2);
            float og = __shfl_sync(mask, act, base + 3);
            if (g == 0) {
                c2 = fmaf(fg, c2, ig * gg);
                float hn = og * tanh_fast(c2);
                hs[2][pn][j] = hn;
                hout[(size_t)t * D_ + j] = hn;
            }
        }
        // no barrier needed here: next step's L0 touches only hs[0], and the
        // L0-end barrier of step t+1 orders hs[2]/hs[1] reuse (parity-disjoint).
        xwv = xwn;
        p = pn;
    }
}

// ---------------------------------------------------------------------------
// Dense(65): out[r,:] = g_hs[r,:] @ Wd + bd.  Wd column in registers.
// Block (65,8) = 520 threads, 64 rows per block.
// ---------------------------------------------------------------------------
#define DR 64
__global__ void __launch_bounds__(520, 1) dense_kernel(
    const float* __restrict__ Wd,
    const float* __restrict__ bd,
    float* __restrict__ out)
{
    __shared__ __align__(16) float hrow[DR][KP];
    const int tx  = threadIdx.x;           // col 0..64
    const int ty  = threadIdx.y;           // 0..7
    const int tid = ty * D_ + tx;

    uint64_t Wc[34];
#pragma unroll
    for (int i = 0; i < 34; i++) {
        int k0 = 2 * i, k1 = 2 * i + 1;
        float w0 = (k0 < D_) ? Wd[(size_t)k0 * D_ + tx] : 0.0f;
        float w1 = (k1 < D_) ? Wd[(size_t)k1 * D_ + tx] : 0.0f;
        Wc[i] = pack2(w0, w1);
    }
    const float bc = bd[tx];
    const size_t row0 = (size_t)blockIdx.x * DR;

    for (int i = tid; i < DR * KP; i += 520) {
        int r = i / KP, cc = i % KP;
        hrow[r][cc] = (cc < D_) ? g_hs[(row0 + r) * D_ + cc] : 0.0f;
    }
    __syncthreads();

    for (int r = ty; r < DR; r += 8)
        out[(row0 + r) * D_ + tx] = bc + dot68(hrow[r], Wc);
}

// ---------------------------------------------------------------------------
extern "C" void kernel_launch(void* const* d_in, const int* in_sizes, int n_in,
                              void* d_out, int out_size)
{
    const float* x  = (const float*)d_in[0];
    const float* W  = (const float*)d_in[1];
    const float* U  = (const float*)d_in[2];
    const float* b  = (const float*)d_in[3];
    const float* Wd = (const float*)d_in[4];
    const float* bd = (const float*)d_in[5];
    float* out = (float*)d_out;

    gemm_xw_kernel<<<BT / GR, G4>>>(x, W, b);
    lstm_kernel<<<B_, G4>>>(W, U, b);
    dense_kernel<<<BT / DR, dim3(D_, 8)>>>(Wd, bd, out);
}